// round 2
// baseline (speedup 1.0000x reference)
#include <cuda_runtime.h>

#define BATCH 64
#define TLEN 2048
#define JLEN 128
#define DDIM 512

#define BT 256   // t tile
#define BJ 64    // j tile
#define BK 16    // k tile
#define NKB (DDIM / BK)  // 32

// Scratch: sim[b][j][t], fp32, 64 MB
__device__ float g_sim[(size_t)BATCH * JLEN * TLEN];
__device__ float g_max[BATCH * JLEN];
__device__ float g_invden[BATCH * JLEN];

// ---------------------------------------------------------------------------
// Kernel 1: per-batch GEMM  sim[j][t] = sum_d (question[j][d]*w[d]) * context[t][d]
// Tile 64(j) x 256(t), BK=16, 256 threads, 4x16 microtile.
// Skips tiles fully outside (t >= clen) or (j >= qlen).
// ---------------------------------------------------------------------------
__global__ __launch_bounds__(256, 2) void gemm_kernel(
    const float* __restrict__ question,
    const float* __restrict__ context,
    const int* __restrict__ qlen,
    const int* __restrict__ clen,
    const float* __restrict__ weight)
{
    const int b  = blockIdx.z;
    const int j0 = blockIdx.y * BJ;
    const int t0 = blockIdx.x * BT;
    const int cl = clen[b];
    const int ql = qlen[b];
    if (t0 >= cl || j0 >= ql) return;

    __shared__ float As[BK][BJ + 4];    // [k][j], stride 68 floats (16B-mult)
    __shared__ float Bs[BK][BT + 4];    // [k][t], stride 260 floats (16B-mult)
    __shared__ float ws[DDIM];

    const int tid = threadIdx.x;

    for (int i = tid; i < DDIM; i += 256) ws[i] = weight[i];
    __syncthreads();

    // global load assignments
    const int arow = tid >> 2;          // 0..63  (j within tile)
    const int acol = (tid & 3) << 2;    // 0,4,8,12 (k within tile)
    const int brow = tid;               // 0..255 (t within tile)

    const float* Aptr = question + ((size_t)(b * JLEN + j0 + arow) * DDIM) + acol;
    const float* Bptr = context  + ((size_t)(b * TLEN + t0 + brow) * DDIM);

    // preload tile 0
    {
        float4 av = *reinterpret_cast<const float4*>(Aptr);
        float4 b0 = *reinterpret_cast<const float4*>(Bptr);
        float4 b1 = *reinterpret_cast<const float4*>(Bptr + 4);
        float4 b2 = *reinterpret_cast<const float4*>(Bptr + 8);
        float4 b3 = *reinterpret_cast<const float4*>(Bptr + 12);
        As[acol + 0][arow] = av.x * ws[acol + 0];
        As[acol + 1][arow] = av.y * ws[acol + 1];
        As[acol + 2][arow] = av.z * ws[acol + 2];
        As[acol + 3][arow] = av.w * ws[acol + 3];
        Bs[ 0][brow] = b0.x;  Bs[ 1][brow] = b0.y;  Bs[ 2][brow] = b0.z;  Bs[ 3][brow] = b0.w;
        Bs[ 4][brow] = b1.x;  Bs[ 5][brow] = b1.y;  Bs[ 6][brow] = b1.z;  Bs[ 7][brow] = b1.w;
        Bs[ 8][brow] = b2.x;  Bs[ 9][brow] = b2.y;  Bs[10][brow] = b2.z;  Bs[11][brow] = b2.w;
        Bs[12][brow] = b3.x;  Bs[13][brow] = b3.y;  Bs[14][brow] = b3.z;  Bs[15][brow] = b3.w;
    }
    __syncthreads();

    const int ty = tid >> 4;   // 0..15 -> j_sub = ty*4
    const int tx = tid & 15;   // 0..15 -> t_sub = tx*16

    float acc[4][16];
    #pragma unroll
    for (int i = 0; i < 4; ++i)
        #pragma unroll
        for (int c = 0; c < 16; ++c) acc[i][c] = 0.0f;

    for (int kb = 0; kb < NKB; ++kb) {
        float4 nav, nb0, nb1, nb2, nb3;
        const bool more = (kb + 1 < NKB);
        if (more) {
            const float* ap = Aptr + (kb + 1) * BK;
            const float* bp = Bptr + (kb + 1) * BK;
            nav = *reinterpret_cast<const float4*>(ap);
            nb0 = *reinterpret_cast<const float4*>(bp);
            nb1 = *reinterpret_cast<const float4*>(bp + 4);
            nb2 = *reinterpret_cast<const float4*>(bp + 8);
            nb3 = *reinterpret_cast<const float4*>(bp + 12);
        }

        #pragma unroll
        for (int kk = 0; kk < BK; ++kk) {
            const float4 a  = *reinterpret_cast<const float4*>(&As[kk][ty << 2]);
            const float4 p0 = *reinterpret_cast<const float4*>(&Bs[kk][(tx << 4) +  0]);
            const float4 p1 = *reinterpret_cast<const float4*>(&Bs[kk][(tx << 4) +  4]);
            const float4 p2 = *reinterpret_cast<const float4*>(&Bs[kk][(tx << 4) +  8]);
            const float4 p3 = *reinterpret_cast<const float4*>(&Bs[kk][(tx << 4) + 12]);
            const float av4[4]  = {a.x, a.y, a.z, a.w};
            const float bv16[16] = {p0.x, p0.y, p0.z, p0.w, p1.x, p1.y, p1.z, p1.w,
                                    p2.x, p2.y, p2.z, p2.w, p3.x, p3.y, p3.z, p3.w};
            #pragma unroll
            for (int i = 0; i < 4; ++i)
                #pragma unroll
                for (int c = 0; c < 16; ++c)
                    acc[i][c] += av4[i] * bv16[c];
        }

        if (more) {
            __syncthreads();
            const int kb1 = (kb + 1) * BK;
            As[acol + 0][arow] = nav.x * ws[kb1 + acol + 0];
            As[acol + 1][arow] = nav.y * ws[kb1 + acol + 1];
            As[acol + 2][arow] = nav.z * ws[kb1 + acol + 2];
            As[acol + 3][arow] = nav.w * ws[kb1 + acol + 3];
            Bs[ 0][brow] = nb0.x;  Bs[ 1][brow] = nb0.y;  Bs[ 2][brow] = nb0.z;  Bs[ 3][brow] = nb0.w;
            Bs[ 4][brow] = nb1.x;  Bs[ 5][brow] = nb1.y;  Bs[ 6][brow] = nb1.z;  Bs[ 7][brow] = nb1.w;
            Bs[ 8][brow] = nb2.x;  Bs[ 9][brow] = nb2.y;  Bs[10][brow] = nb2.z;  Bs[11][brow] = nb2.w;
            Bs[12][brow] = nb3.x;  Bs[13][brow] = nb3.y;  Bs[14][brow] = nb3.z;  Bs[15][brow] = nb3.w;
            __syncthreads();
        }
    }

    // epilogue: sim[b][j0+ty*4+i][t0+tx*16 + 0..15]
    #pragma unroll
    for (int i = 0; i < 4; ++i) {
        float* row = g_sim + ((size_t)(b * JLEN + j0 + (ty << 2) + i)) * TLEN + t0 + (tx << 4);
        #pragma unroll
        for (int c = 0; c < 4; ++c) {
            float4 v = make_float4(acc[i][4*c+0], acc[i][4*c+1], acc[i][4*c+2], acc[i][4*c+3]);
            *reinterpret_cast<float4*>(row + 4*c) = v;
        }
    }
}

// ---------------------------------------------------------------------------
// Kernel 2: per (b, j<qlen): max over t<clen, then sum of exp, store max & 1/sum
// ---------------------------------------------------------------------------
__device__ __forceinline__ float warpMax(float v) {
    #pragma unroll
    for (int o = 16; o > 0; o >>= 1) v = fmaxf(v, __shfl_xor_sync(0xffffffffu, v, o));
    return v;
}
__device__ __forceinline__ float warpSum(float v) {
    #pragma unroll
    for (int o = 16; o > 0; o >>= 1) v += __shfl_xor_sync(0xffffffffu, v, o);
    return v;
}

__global__ __launch_bounds__(256) void stats_kernel(
    const int* __restrict__ qlen,
    const int* __restrict__ clen)
{
    const int b = blockIdx.y;
    const int j = blockIdx.x;
    if (j >= qlen[b]) return;
    const int cl = clen[b];

    const float* row = g_sim + ((size_t)(b * JLEN + j)) * TLEN;
    const int tid = threadIdx.x;

    __shared__ float red[8];
    __shared__ float smax;

    float m = -3.4028235e38f;
    for (int t = tid; t < cl; t += 256) m = fmaxf(m, row[t]);
    m = warpMax(m);
    if ((tid & 31) == 0) red[tid >> 5] = m;
    __syncthreads();
    if (tid == 0) {
        float mm = red[0];
        #pragma unroll
        for (int i = 1; i < 8; ++i) mm = fmaxf(mm, red[i]);
        smax = mm;
    }
    __syncthreads();
    m = smax;

    float s = 0.0f;
    for (int t = tid; t < cl; t += 256) s += __expf(row[t] - m);
    s = warpSum(s);
    if ((tid & 31) == 0) red[tid >> 5] = s;
    __syncthreads();
    if (tid == 0) {
        float ss = 0.0f;
        #pragma unroll
        for (int i = 0; i < 8; ++i) ss += red[i];
        g_max[b * JLEN + j]    = m;
        g_invden[b * JLEN + j] = 1.0f / ss;
    }
}

// ---------------------------------------------------------------------------
// Kernel 3: out[b,t] = sum_{j<qlen} exp(sim[b][j][t]-max)*invden  (t<clen), else 0
// ---------------------------------------------------------------------------
__global__ __launch_bounds__(256) void out_kernel(
    const int* __restrict__ qlen,
    const int* __restrict__ clen,
    float* __restrict__ out)
{
    const int b = blockIdx.y;
    const int t = blockIdx.x * 256 + threadIdx.x;
    const int ql = qlen[b];
    const int cl = clen[b];

    __shared__ float sm[JLEN];
    __shared__ float sd[JLEN];
    for (int jj = threadIdx.x; jj < ql; jj += 256) {
        sm[jj] = g_max[b * JLEN + jj];
        sd[jj] = g_invden[b * JLEN + jj];
    }
    __syncthreads();

    float r = 0.0f;
    if (t < cl) {
        const float* col = g_sim + (size_t)b * JLEN * TLEN + t;
        #pragma unroll 4
        for (int jj = 0; jj < ql; ++jj)
            r += __expf(col[(size_t)jj * TLEN] - sm[jj]) * sd[jj];
    }
    out[b * TLEN + t] = r;
}

// ---------------------------------------------------------------------------
extern "C" void kernel_launch(void* const* d_in, const int* in_sizes, int n_in,
                              void* d_out, int out_size)
{
    const float* question = (const float*)d_in[0];
    const float* context  = (const float*)d_in[1];
    const int*   qlen     = (const int*)d_in[2];
    const int*   clen     = (const int*)d_in[3];
    const float* weight   = (const float*)d_in[4];
    float* out = (float*)d_out;

    dim3 g1(TLEN / BT, JLEN / BJ, BATCH);   // 8 x 2 x 64
    gemm_kernel<<<g1, 256>>>(question, context, qlen, clen, weight);

    dim3 g2(JLEN, BATCH);                   // 128 x 64
    stats_kernel<<<g2, 256>>>(qlen, clen);

    dim3 g3(TLEN / 256, BATCH);             // 8 x 64
    out_kernel<<<g3, 256>>>(qlen, clen, out);
}

// round 3
// speedup vs baseline: 2.3569x; 2.3569x over previous
#include <cuda_runtime.h>

#define BATCH 64
#define TLEN 2048
#define JLEN 128
#define DDIM 512

#define BT 128   // t tile
#define BJ 64    // j tile
#define BK 16    // k tile
#define NKB (DDIM / BK)  // 32

// Scratch: sim[b][j][t], fp32, 64 MB
__device__ float g_sim[(size_t)BATCH * JLEN * TLEN];
__device__ float g_max[BATCH * JLEN];
__device__ float g_invden[BATCH * JLEN];

// ---------------------------------------------------------------------------
// Kernel 1: per-batch GEMM  sim[j][t] = sum_d (question[j][d]*w[d]) * context[t][d]
// Tile 64(j) x 128(t), BK=16, 256 threads, 4x8 microtile.
// Warp layout: 8 warps = 4(j) x 2(t). Lane: ty_w=lane>>3 (j), tx_w=lane&7 (t).
// Thread fragment: j = warp_j*16 + ty_w*4 + (0..3)
//                  t = warp_t*64 + tx_w*4 + (0..3)  and  +32 + (0..3)
// -> all shared loads are conflict-free (A broadcast, B lane-stride 16B).
// ---------------------------------------------------------------------------
__global__ __launch_bounds__(256) void gemm_kernel(
    const float* __restrict__ question,
    const float* __restrict__ context,
    const int* __restrict__ qlen,
    const int* __restrict__ clen,
    const float* __restrict__ weight)
{
    const int b  = blockIdx.z;
    const int j0 = blockIdx.y * BJ;
    const int t0 = blockIdx.x * BT;
    const int cl = clen[b];
    const int ql = qlen[b];
    if (t0 >= cl || j0 >= ql) return;

    __shared__ float As[BK][BJ + 4];   // [k][j], row stride 68 floats (16B-mult)
    __shared__ float Bs[BK][BT + 4];   // [k][t], row stride 132 floats (16B-mult)
    __shared__ float ws[DDIM];

    const int tid = threadIdx.x;

    // stage weight vector
    for (int i = tid; i < DDIM; i += 256) ws[i] = weight[i];
    __syncthreads();

    // global load assignments (same as the 305us version)
    const int arow = tid >> 2;          // 0..63  (j within tile)
    const int acol = (tid & 3) << 2;    // 0,4,8,12 (k within tile)
    const int brow = tid >> 1;          // 0..127 (t within tile)
    const int bcol = (tid & 1) << 3;    // 0,8    (k within tile)

    const float* Aptr = question + ((size_t)(b * JLEN + j0 + arow) * DDIM) + acol;
    const float* Bptr = context  + ((size_t)(b * TLEN + t0 + brow) * DDIM) + bcol;

    // preload tile 0
    {
        float4 av  = *reinterpret_cast<const float4*>(Aptr);
        float4 bv0 = *reinterpret_cast<const float4*>(Bptr);
        float4 bv1 = *reinterpret_cast<const float4*>(Bptr + 4);
        As[acol + 0][arow] = av.x * ws[acol + 0];
        As[acol + 1][arow] = av.y * ws[acol + 1];
        As[acol + 2][arow] = av.z * ws[acol + 2];
        As[acol + 3][arow] = av.w * ws[acol + 3];
        Bs[bcol + 0][brow] = bv0.x;
        Bs[bcol + 1][brow] = bv0.y;
        Bs[bcol + 2][brow] = bv0.z;
        Bs[bcol + 3][brow] = bv0.w;
        Bs[bcol + 4][brow] = bv1.x;
        Bs[bcol + 5][brow] = bv1.y;
        Bs[bcol + 6][brow] = bv1.z;
        Bs[bcol + 7][brow] = bv1.w;
    }
    __syncthreads();

    // compute-side mapping (conflict-free)
    const int lane   = tid & 31;
    const int warp   = tid >> 5;
    const int warp_j = (warp & 3) << 4;  // 0,16,32,48
    const int warp_t = (warp >> 2) << 6; // 0,64
    const int ty4    = (lane >> 3) << 2; // 0,4,8,12  (j sub-offset)
    const int tx4    = (lane & 7) << 2;  // 0..28     (t sub-offset)

    const int jf = warp_j + ty4;         // fragment j base within tile
    const int tf = warp_t + tx4;         // fragment t base within tile (plus +32 half)

    float acc[4][8];
    #pragma unroll
    for (int i = 0; i < 4; ++i)
        #pragma unroll
        for (int c = 0; c < 8; ++c) acc[i][c] = 0.0f;

    for (int kb = 0; kb < NKB; ++kb) {
        float4 nav, nbv0, nbv1;
        const bool more = (kb + 1 < NKB);
        if (more) {
            nav  = *reinterpret_cast<const float4*>(Aptr + (kb + 1) * BK);
            nbv0 = *reinterpret_cast<const float4*>(Bptr + (kb + 1) * BK);
            nbv1 = *reinterpret_cast<const float4*>(Bptr + (kb + 1) * BK + 4);
        }

        #pragma unroll
        for (int kk = 0; kk < BK; ++kk) {
            const float4 a = *reinterpret_cast<const float4*>(&As[kk][jf]);
            const float4 p = *reinterpret_cast<const float4*>(&Bs[kk][tf]);
            const float4 q = *reinterpret_cast<const float4*>(&Bs[kk][tf + 32]);
            const float av4[4] = {a.x, a.y, a.z, a.w};
            const float bv8[8] = {p.x, p.y, p.z, p.w, q.x, q.y, q.z, q.w};
            #pragma unroll
            for (int i = 0; i < 4; ++i)
                #pragma unroll
                for (int c = 0; c < 8; ++c)
                    acc[i][c] += av4[i] * bv8[c];
        }

        if (more) {
            __syncthreads();
            const int kb1 = (kb + 1) * BK;
            As[acol + 0][arow] = nav.x * ws[kb1 + acol + 0];
            As[acol + 1][arow] = nav.y * ws[kb1 + acol + 1];
            As[acol + 2][arow] = nav.z * ws[kb1 + acol + 2];
            As[acol + 3][arow] = nav.w * ws[kb1 + acol + 3];
            Bs[bcol + 0][brow] = nbv0.x;
            Bs[bcol + 1][brow] = nbv0.y;
            Bs[bcol + 2][brow] = nbv0.z;
            Bs[bcol + 3][brow] = nbv0.w;
            Bs[bcol + 4][brow] = nbv1.x;
            Bs[bcol + 5][brow] = nbv1.y;
            Bs[bcol + 6][brow] = nbv1.z;
            Bs[bcol + 7][brow] = nbv1.w;
            __syncthreads();
        }
    }

    // epilogue: sim[b][j0+jf+i][t0+tf + 0..3] and [+32..35]
    #pragma unroll
    for (int i = 0; i < 4; ++i) {
        float* row = g_sim + ((size_t)(b * JLEN + j0 + jf + i)) * TLEN + t0 + tf;
        float4 lo = make_float4(acc[i][0], acc[i][1], acc[i][2], acc[i][3]);
        float4 hi = make_float4(acc[i][4], acc[i][5], acc[i][6], acc[i][7]);
        *reinterpret_cast<float4*>(row)      = lo;
        *reinterpret_cast<float4*>(row + 32) = hi;
    }
}

// ---------------------------------------------------------------------------
// Kernel 2: per (b, j<qlen): max over t<clen, then sum of exp, store max & 1/sum
// ---------------------------------------------------------------------------
__device__ __forceinline__ float warpMax(float v) {
    #pragma unroll
    for (int o = 16; o > 0; o >>= 1) v = fmaxf(v, __shfl_xor_sync(0xffffffffu, v, o));
    return v;
}
__device__ __forceinline__ float warpSum(float v) {
    #pragma unroll
    for (int o = 16; o > 0; o >>= 1) v += __shfl_xor_sync(0xffffffffu, v, o);
    return v;
}

__global__ __launch_bounds__(256) void stats_kernel(
    const int* __restrict__ qlen,
    const int* __restrict__ clen)
{
    const int b = blockIdx.y;
    const int j = blockIdx.x;
    if (j >= qlen[b]) return;
    const int cl = clen[b];

    const float* row = g_sim + ((size_t)(b * JLEN + j)) * TLEN;
    const int tid = threadIdx.x;

    __shared__ float red[8];
    __shared__ float smax;

    float m = -3.4028235e38f;
    for (int t = tid; t < cl; t += 256) m = fmaxf(m, row[t]);
    m = warpMax(m);
    if ((tid & 31) == 0) red[tid >> 5] = m;
    __syncthreads();
    if (tid == 0) {
        float mm = red[0];
        #pragma unroll
        for (int i = 1; i < 8; ++i) mm = fmaxf(mm, red[i]);
        smax = mm;
    }
    __syncthreads();
    m = smax;

    float s = 0.0f;
    for (int t = tid; t < cl; t += 256) s += __expf(row[t] - m);
    s = warpSum(s);
    if ((tid & 31) == 0) red[tid >> 5] = s;
    __syncthreads();
    if (tid == 0) {
        float ss = 0.0f;
        #pragma unroll
        for (int i = 0; i < 8; ++i) ss += red[i];
        g_max[b * JLEN + j]    = m;
        g_invden[b * JLEN + j] = 1.0f / ss;
    }
}

// ---------------------------------------------------------------------------
// Kernel 3: out[b,t] = sum_{j<qlen} exp(sim[b][j][t]-max)*invden  (t<clen), else 0
// ---------------------------------------------------------------------------
__global__ __launch_bounds__(256) void out_kernel(
    const int* __restrict__ qlen,
    const int* __restrict__ clen,
    float* __restrict__ out)
{
    const int b = blockIdx.y;
    const int t = blockIdx.x * 256 + threadIdx.x;
    const int ql = qlen[b];
    const int cl = clen[b];

    __shared__ float sm[JLEN];
    __shared__ float sd[JLEN];
    for (int jj = threadIdx.x; jj < ql; jj += 256) {
        sm[jj] = g_max[b * JLEN + jj];
        sd[jj] = g_invden[b * JLEN + jj];
    }
    __syncthreads();

    float r = 0.0f;
    if (t < cl) {
        const float* col = g_sim + (size_t)b * JLEN * TLEN + t;
        #pragma unroll 4
        for (int jj = 0; jj < ql; ++jj)
            r += __expf(col[(size_t)jj * TLEN] - sm[jj]) * sd[jj];
    }
    out[b * TLEN + t] = r;
}

// ---------------------------------------------------------------------------
extern "C" void kernel_launch(void* const* d_in, const int* in_sizes, int n_in,
                              void* d_out, int out_size)
{
    const float* question = (const float*)d_in[0];
    const float* context  = (const float*)d_in[1];
    const int*   qlen     = (const int*)d_in[2];
    const int*   clen     = (const int*)d_in[3];
    const float* weight   = (const float*)d_in[4];
    float* out = (float*)d_out;

    dim3 g1(TLEN / BT, JLEN / BJ, BATCH);   // 16 x 2 x 64
    gemm_kernel<<<g1, 256>>>(question, context, qlen, clen, weight);

    dim3 g2(JLEN, BATCH);                   // 128 x 64
    stats_kernel<<<g2, 256>>>(qlen, clen);

    dim3 g3(TLEN / 256, BATCH);             // 8 x 64
    out_kernel<<<g3, 256>>>(qlen, clen, out);
}